// round 14
// baseline (speedup 1.0000x reference)
#include <cuda_runtime.h>
#include <cuda_fp16.h>

#define NN 100000
#define EE 1600000
#define VV 50000
#define FF 128
#define CC 20
#define CAP 64            // fixed CSR bucket capacity (in-deg ~Poisson(16), max<<64)
#define CAPSH 6

// ---------------- scratch (device globals; no allocation allowed) ----------------
__device__ float  g_deg[NN];
__device__ float  g_dinv[NN];
__device__ int    g_cnt[NN];
__device__ int2   g_ecsr[NN * CAP];  // packed (src, coef bits); bucket node<<6+slot
__device__ __half g_embh[VV * FF]; // (emb @ W0) in fp16, hoisted to vocab
__device__ __half g_hh[NN * FF];   // layer h in fp16
__device__ __half g_act[NN * FF];  // aggregated activations (fp16)
__device__ float  g_h2[NN * CC];   // layer-2 h

__device__ __forceinline__ float lrelu(float x) { return x > 0.0f ? x : 0.01f * x; }

__device__ __forceinline__ unsigned smem_u32(const void* p) {
    return (unsigned)__cvta_generic_to_shared(p);
}

// ---------------- prep: deg=1 (self loop), cnt=0 ----------------
__global__ void k_prep() {
    int i = blockIdx.x * 256 + threadIdx.x;
    if (i < NN) { g_deg[i] = 1.0f; g_cnt[i] = 0; }
}

// ---------------- hist: deg only (count moved into fill) ----------------
__global__ void k_hist(const int* __restrict__ dst, const float* __restrict__ ew) {
    int e = blockIdx.x * 256 + threadIdx.x;
    if (e < EE) atomicAdd(&g_deg[dst[e]], ew[e]);
}

__global__ void k_dinv() {
    int i = blockIdx.x * 256 + threadIdx.x;
    if (i < NN) g_dinv[i] = rsqrtf(g_deg[i]);
}

// ---------------- CSR fill into fixed-capacity buckets; packed int2 -----------
__global__ void k_fill(const int* __restrict__ src, const int* __restrict__ dst,
                       const float* __restrict__ ew) {
    int e = blockIdx.x * 256 + threadIdx.x;
    if (e < EE) {
        int s = src[e], d = dst[e];
        int pos = atomicAdd(&g_cnt[d], 1);
        float coef = g_dinv[s] * ew[e] * g_dinv[d];
        g_ecsr[(d << CAPSH) + pos] = make_int2(s, __float_as_int(coef));
    }
}

// ---------------- tensor-core GEMM: [M,128](TIN,lrelu?) x [128,128] -> fp16 ----
// 256 threads / 8 warps. Block tile 128x128; warp tile 32x64.
// A and W staged fp16 in smem, row pad 136 halves (272B) -> ldmatrix conflict-free.
#define PAD 136
template <bool LRELU, typename TIN>
__global__ __launch_bounds__(256)
void k_gemm_mma(const TIN* __restrict__ A, const float* __restrict__ Wm,
                __half* __restrict__ Hout, int M) {
    extern __shared__ __half smh[];
    __half* As = smh;              // [128][PAD]
    __half* Ws = smh + 128 * PAD;  // [128][PAD]  (row-major [k][n])

    const int tid = threadIdx.x;
    const int row0 = blockIdx.x * 128;

    // stage A -> fp16, fused lrelu, zero-pad OOB rows
#pragma unroll
    for (int it = tid; it < 128 * 32; it += 256) {
        int r = it >> 5, c4 = it & 31;
        int row = row0 + r;
        float x0 = 0.f, x1 = 0.f, x2 = 0.f, x3 = 0.f;
        if (row < M) {
            if (sizeof(TIN) == 4) {
                float4 v = *(const float4*)((const float*)A + (size_t)row * FF + c4 * 4);
                x0 = v.x; x1 = v.y; x2 = v.z; x3 = v.w;
            } else {
                uint2 rw = *(const uint2*)((const __half*)A + (size_t)row * FF + c4 * 4);
                float2 f0 = __half22float2(*reinterpret_cast<__half2*>(&rw.x));
                float2 f1 = __half22float2(*reinterpret_cast<__half2*>(&rw.y));
                x0 = f0.x; x1 = f0.y; x2 = f1.x; x3 = f1.y;
            }
            if (LRELU) { x0 = lrelu(x0); x1 = lrelu(x1); x2 = lrelu(x2); x3 = lrelu(x3); }
        }
        __half2 h01 = __floats2half2_rn(x0, x1);
        __half2 h23 = __floats2half2_rn(x2, x3);
        uint2 pk = make_uint2(*reinterpret_cast<unsigned*>(&h01),
                              *reinterpret_cast<unsigned*>(&h23));
        *(uint2*)(As + r * PAD + c4 * 4) = pk;
    }
    // stage W (fp32 -> fp16, row-major [k][n])
#pragma unroll
    for (int it = tid; it < 128 * 32; it += 256) {
        int k = it >> 5, n4 = it & 31;
        float4 v = *(const float4*)(Wm + (size_t)k * FF + n4 * 4);
        __half2 h01 = __floats2half2_rn(v.x, v.y);
        __half2 h23 = __floats2half2_rn(v.z, v.w);
        uint2 pk = make_uint2(*reinterpret_cast<unsigned*>(&h01),
                              *reinterpret_cast<unsigned*>(&h23));
        *(uint2*)(Ws + k * PAD + n4 * 4) = pk;
    }
    __syncthreads();

    const int lane = tid & 31;
    const int warp = tid >> 5;
    const int wm = warp & 3;    // 4 warps down M: rows wm*32
    const int wn = warp >> 2;   // 2 warps across N: cols wn*64

    float c[2][8][4];
#pragma unroll
    for (int mi = 0; mi < 2; mi++)
#pragma unroll
        for (int ni = 0; ni < 8; ni++)
#pragma unroll
            for (int j = 0; j < 4; j++) c[mi][ni][j] = 0.f;

    const int a_r = lane & 15;
    const int a_c = (lane >> 4) * 8;
    const int b_k = lane & 15;

#pragma unroll
    for (int ks = 0; ks < 8; ks++) {
        const int k0 = ks * 16;
        unsigned a[2][4];
#pragma unroll
        for (int mi = 0; mi < 2; mi++) {
            const __half* ap = As + (wm * 32 + mi * 16 + a_r) * PAD + k0 + a_c;
            asm volatile("ldmatrix.sync.aligned.m8n8.x4.shared.b16 {%0,%1,%2,%3}, [%4];"
                         : "=r"(a[mi][0]), "=r"(a[mi][1]), "=r"(a[mi][2]), "=r"(a[mi][3])
                         : "r"(smem_u32(ap)));
        }
        unsigned b[8][2];
#pragma unroll
        for (int ni = 0; ni < 8; ni++) {
            const __half* bp = Ws + (k0 + b_k) * PAD + wn * 64 + ni * 8;
            asm volatile("ldmatrix.sync.aligned.m8n8.x2.trans.shared.b16 {%0,%1}, [%2];"
                         : "=r"(b[ni][0]), "=r"(b[ni][1])
                         : "r"(smem_u32(bp)));
        }
#pragma unroll
        for (int mi = 0; mi < 2; mi++)
#pragma unroll
            for (int ni = 0; ni < 8; ni++) {
                asm volatile(
                    "mma.sync.aligned.m16n8k16.row.col.f32.f16.f16.f32 "
                    "{%0,%1,%2,%3}, {%4,%5,%6,%7}, {%8,%9}, {%0,%1,%2,%3};"
                    : "+f"(c[mi][ni][0]), "+f"(c[mi][ni][1]),
                      "+f"(c[mi][ni][2]), "+f"(c[mi][ni][3])
                    : "r"(a[mi][0]), "r"(a[mi][1]), "r"(a[mi][2]), "r"(a[mi][3]),
                      "r"(b[ni][0]), "r"(b[ni][1]));
            }
    }

    // epilogue: fp32 -> fp16, packed u32 stores
#pragma unroll
    for (int mi = 0; mi < 2; mi++) {
        int rbase = row0 + wm * 32 + mi * 16 + (lane >> 2);
#pragma unroll
        for (int ni = 0; ni < 8; ni++) {
            int col = wn * 64 + ni * 8 + (lane & 3) * 2;
            __half2 lo = __floats2half2_rn(c[mi][ni][0], c[mi][ni][1]);
            __half2 hi = __floats2half2_rn(c[mi][ni][2], c[mi][ni][3]);
            if (rbase < M)
                *(unsigned*)(Hout + (size_t)rbase * FF + col) =
                    *reinterpret_cast<unsigned*>(&lo);
            if (rbase + 8 < M)
                *(unsigned*)(Hout + (size_t)(rbase + 8) * FF + col) =
                    *reinterpret_cast<unsigned*>(&hi);
        }
    }
}

// ---------------- GEMM: [M,128](fp16,lrelu) x [128,20] -> fp32, f32x2 FMA -----
__global__ __launch_bounds__(128)
void k_gemm20(const __half* __restrict__ A, const float* __restrict__ Wm,
              float* __restrict__ Hout, int M) {
    extern __shared__ float sm[];
    float* As = sm;             // 128 * 133
    float* Ws = sm + 128 * 133; // 128 * 20

    const int tid = threadIdx.x;

    for (int i = tid; i < FF * CC / 4; i += 128)
        ((float4*)Ws)[i] = ((const float4*)Wm)[i];

    const int row0 = blockIdx.x * 128;
    for (int i = tid; i < 128 * 32; i += 128) {
        int r = i >> 5, k4 = i & 31;
        float x0 = 0.f, x1 = 0.f, x2 = 0.f, x3 = 0.f;
        int row = row0 + r;
        if (row < M) {
            uint2 rw = *(const uint2*)(A + (size_t)row * FF + k4 * 4);
            float2 f0 = __half22float2(*reinterpret_cast<__half2*>(&rw.x));
            float2 f1 = __half22float2(*reinterpret_cast<__half2*>(&rw.y));
            x0 = lrelu(f0.x); x1 = lrelu(f0.y); x2 = lrelu(f1.x); x3 = lrelu(f1.y);
        }
        float* p = As + r * 133 + k4 * 4;
        p[0] = x0; p[1] = x1; p[2] = x2; p[3] = x3;
    }
    __syncthreads();

    unsigned long long acc2[10];
#pragma unroll
    for (int j = 0; j < 10; j++) acc2[j] = 0ULL;

    const float* Ap = As + tid * 133;
#pragma unroll 4
    for (int k = 0; k < FF; k++) {
        float xv = Ap[k];
        unsigned xb = __float_as_uint(xv);
        unsigned long long av;
        asm("mov.b64 %0, {%1, %1};" : "=l"(av) : "r"(xb));
        const unsigned long long* wq =
            (const unsigned long long*)(Ws + k * CC);
#pragma unroll
        for (int j = 0; j < 10; j++) {
            asm("fma.rn.f32x2 %0, %1, %2, %0;" : "+l"(acc2[j]) : "l"(av), "l"(wq[j]));
        }
    }

    int row = row0 + tid;
    if (row < M) {
        float o[20];
#pragma unroll
        for (int j = 0; j < 10; j++) {
            unsigned lo, hi;
            asm("mov.b64 {%0, %1}, %2;" : "=r"(lo), "=r"(hi) : "l"(acc2[j]));
            o[2 * j]     = __uint_as_float(lo);
            o[2 * j + 1] = __uint_as_float(hi);
        }
#pragma unroll
        for (int c4 = 0; c4 < 5; c4++) {
            *(float4*)(Hout + (size_t)row * CC + c4 * 4) =
                make_float4(o[c4 * 4], o[c4 * 4 + 1], o[c4 * 4 + 2], o[c4 * 4 + 3]);
        }
    }
}

// ---------------- CSR aggregation, 128-wide: TWO warps per node ---------------
// Inner loop body is byte-identical to the verified optimum (2-edge unroll);
// only the edge-range split, partial-sum combine, and epilogue ownership differ.
// Block = 256 threads = 8 warps = 4 nodes. NN % 4 == 0 -> no divergent returns.
template <bool GATHER>
__global__ __launch_bounds__(256)
void k_agg128(const __half* __restrict__ hh, const int* __restrict__ nid,
              const float* __restrict__ b, __half* __restrict__ out) {
    __shared__ float sm_part[4][128];   // partial sums from sub-warp 1

    const int warp = threadIdx.x >> 5;
    const int lane = threadIdx.x & 31;
    const int pairLocal = warp >> 1;    // 0..3 (node within block)
    const int sub = warp & 1;           // 0 or 1
    const int node = blockIdx.x * 4 + pairLocal;

    int cnt = g_cnt[node];
    int beg0 = node << CAPSH;
    int h = (cnt + 1) >> 1;             // sub0: [0,h), sub1: [h,cnt)
    int lo = sub ? h : 0;
    int hiE = sub ? cnt : h;
    int beg = beg0 + lo;
    int n = hiE - lo;

    float4 acc = make_float4(0.f, 0.f, 0.f, 0.f);
    int i = 0;
    int end2 = n & ~1;
    for (; i < end2; i += 2) {
        int2 e0 = g_ecsr[beg + i];
        int2 e1 = g_ecsr[beg + i + 1];
        int s0 = e0.x;
        int s1 = e1.x;
        float c0 = __int_as_float(e0.y);
        float c1 = __int_as_float(e1.y);
        if (GATHER) { s0 = nid[s0]; s1 = nid[s1]; }
        uint2 r0 = *(const uint2*)(hh + (size_t)s0 * FF + lane * 4);
        uint2 r1 = *(const uint2*)(hh + (size_t)s1 * FF + lane * 4);
        float2 f00 = __half22float2(*reinterpret_cast<__half2*>(&r0.x));
        float2 f01 = __half22float2(*reinterpret_cast<__half2*>(&r0.y));
        float2 f10 = __half22float2(*reinterpret_cast<__half2*>(&r1.x));
        float2 f11 = __half22float2(*reinterpret_cast<__half2*>(&r1.y));
        acc.x = fmaf(c0, f00.x, acc.x); acc.y = fmaf(c0, f00.y, acc.y);
        acc.z = fmaf(c0, f01.x, acc.z); acc.w = fmaf(c0, f01.y, acc.w);
        acc.x = fmaf(c1, f10.x, acc.x); acc.y = fmaf(c1, f10.y, acc.y);
        acc.z = fmaf(c1, f11.x, acc.z); acc.w = fmaf(c1, f11.y, acc.w);
    }
    if (i < n) {
        int2 e0 = g_ecsr[beg + i];
        int s0 = e0.x;
        float c0 = __int_as_float(e0.y);
        if (GATHER) s0 = nid[s0];
        uint2 r0 = *(const uint2*)(hh + (size_t)s0 * FF + lane * 4);
        float2 f00 = __half22float2(*reinterpret_cast<__half2*>(&r0.x));
        float2 f01 = __half22float2(*reinterpret_cast<__half2*>(&r0.y));
        acc.x = fmaf(c0, f00.x, acc.x); acc.y = fmaf(c0, f00.y, acc.y);
        acc.z = fmaf(c0, f01.x, acc.z); acc.w = fmaf(c0, f01.y, acc.w);
    }

    // sub-warp 1 parks its partial; sub-warp 0 combines + epilogue
    if (sub) *(float4*)(&sm_part[pairLocal][lane * 4]) = acc;
    __syncthreads();
    if (!sub) {
        float4 p = *(const float4*)(&sm_part[pairLocal][lane * 4]);
        acc.x += p.x; acc.y += p.y; acc.z += p.z; acc.w += p.w;

        float di = g_dinv[node];
        float d2 = di * di;
        int sn = GATHER ? nid[node] : node;
        uint2 rs = *(const uint2*)(hh + (size_t)sn * FF + lane * 4);
        float2 fs0 = __half22float2(*reinterpret_cast<__half2*>(&rs.x));
        float2 fs1 = __half22float2(*reinterpret_cast<__half2*>(&rs.y));
        float4 bv = *(const float4*)(b + lane * 4);
        acc.x = fmaf(fs0.x, d2, acc.x) + bv.x;
        acc.y = fmaf(fs0.y, d2, acc.y) + bv.y;
        acc.z = fmaf(fs1.x, d2, acc.z) + bv.z;
        acc.w = fmaf(fs1.y, d2, acc.w) + bv.w;
        __half2 o01 = __floats2half2_rn(acc.x, acc.y);
        __half2 o23 = __floats2half2_rn(acc.z, acc.w);
        uint2 pk = make_uint2(*reinterpret_cast<unsigned*>(&o01),
                              *reinterpret_cast<unsigned*>(&o23));
        *(uint2*)(out + (size_t)node * FF + lane * 4) = pk;
    }
}

// ---------------- CSR aggregation 20-wide + bias + fused log_softmax ----------
__global__ __launch_bounds__(256)
void k_agg20_lsm(const float* __restrict__ b, float* __restrict__ out) {
    int warp = (blockIdx.x * 256 + threadIdx.x) >> 5;
    int lane = threadIdx.x & 31;
    if (warp >= NN) return;
    int cnt = g_cnt[warp];
    int beg = warp << CAPSH;

    float acc = 0.f;
    for (int i = 0; i < cnt; i++) {
        int2 e0 = g_ecsr[beg + i];
        if (lane < CC)
            acc = fmaf(__int_as_float(e0.y), g_h2[(size_t)e0.x * CC + lane], acc);
    }
    float di = g_dinv[warp];
    float d2 = di * di;
    if (lane < CC)
        acc = fmaf(g_h2[(size_t)warp * CC + lane], d2, acc) + b[lane];

    float m = (lane < CC) ? acc : -1e30f;
#pragma unroll
    for (int off = 16; off > 0; off >>= 1)
        m = fmaxf(m, __shfl_xor_sync(0xffffffffu, m, off));
    float e = (lane < CC) ? expf(acc - m) : 0.f;
    float ssum = e;
#pragma unroll
    for (int off = 16; off > 0; off >>= 1)
        ssum += __shfl_xor_sync(0xffffffffu, ssum, off);
    float l = logf(ssum) + m;
    if (lane < CC)
        out[(size_t)warp * CC + lane] = acc - l;
}

// ---------------- launch ----------------
extern "C" void kernel_launch(void* const* d_in, const int* in_sizes, int n_in,
                              void* d_out, int out_size) {
    const int*   nid = (const int*)d_in[0];
    const int*   eidx = (const int*)d_in[1];
    const int*   src = eidx;
    const int*   dst = eidx + EE;
    const float* ew  = (const float*)d_in[2];
    const float* emb = (const float*)d_in[3];
    const float* W0  = (const float*)d_in[4];
    const float* b0  = (const float*)d_in[5];
    const float* W1  = (const float*)d_in[6];
    const float* b1  = (const float*)d_in[7];
    const float* W2  = (const float*)d_in[8];
    const float* b2  = (const float*)d_in[9];
    float* out = (float*)d_out;

    __half *p_embh, *p_hh, *p_act;
    float *p_h2;
    cudaGetSymbolAddress((void**)&p_embh, g_embh);
    cudaGetSymbolAddress((void**)&p_hh,   g_hh);
    cudaGetSymbolAddress((void**)&p_act,  g_act);
    cudaGetSymbolAddress((void**)&p_h2,   g_h2);

    const int SMEM_MMA = 2 * 128 * PAD * (int)sizeof(__half);  // 69632 B
    const int SMEM_G20 = (128 * 133 + FF * CC) * 4;            // 78336 B
    cudaFuncSetAttribute((const void*)(k_gemm_mma<false, float>),
                         cudaFuncAttributeMaxDynamicSharedMemorySize, SMEM_MMA);
    cudaFuncSetAttribute((const void*)(k_gemm_mma<true, __half>),
                         cudaFuncAttributeMaxDynamicSharedMemorySize, SMEM_MMA);
    cudaFuncSetAttribute((const void*)k_gemm20,
                         cudaFuncAttributeMaxDynamicSharedMemorySize, SMEM_G20);

    // CSR build (no scan): prep -> hist(deg) -> dinv -> vocab GEMM -> fill
    k_prep<<<(NN + 255) / 256, 256>>>();
    k_hist<<<(EE + 255) / 256, 256>>>(dst, ew);
    k_dinv<<<(NN + 255) / 256, 256>>>();
    k_gemm_mma<false, float><<<(VV + 127) / 128, 256, SMEM_MMA>>>(emb, W0, p_embh, VV);
    k_fill<<<(EE + 255) / 256, 256>>>(src, dst, ew);

    // layer 0: aggregate straight from vocab-level embh via nid indirection
    k_agg128<true><<<NN / 4, 256>>>(p_embh, nid, b0, p_act);

    // layer 1
    k_gemm_mma<true, __half><<<(NN + 127) / 128, 256, SMEM_MMA>>>(p_act, W1, p_hh, NN);
    k_agg128<false><<<NN / 4, 256>>>(p_hh, nid, b1, p_act);

    // layer 2 + fused log_softmax
    k_gemm20<<<(NN + 127) / 128, 128, SMEM_G20>>>(p_act, W2, p_h2, NN);
    k_agg20_lsm<<<(NN * 32 + 255) / 256, 256>>>(b2, out);
}

// round 15
// speedup vs baseline: 1.1808x; 1.1808x over previous
#include <cuda_runtime.h>
#include <cuda_fp16.h>

#define NN 100000
#define EE 1600000
#define VV 50000
#define FF 128
#define CC 20
#define CAP 64            // fixed CSR bucket capacity (in-deg ~Poisson(16), max<<64)
#define CAPSH 6

// ---------------- scratch (device globals; no allocation allowed) ----------------
__device__ float  g_deg[NN];
__device__ float  g_dinv[NN];
__device__ int    g_cnt[NN];
__device__ int2   g_ecsr[NN * CAP];  // packed (src, coef bits); bucket node<<6+slot
__device__ __half g_embh[VV * FF]; // (emb @ W0) in fp16, hoisted to vocab
__device__ __half g_hh[NN * FF];   // layer h in fp16
__device__ __half g_act[NN * FF];  // aggregated activations (fp16)
__device__ __half g_h2[NN * CC];   // layer-2 h (fp16)  [THIS ROUND]

__device__ __forceinline__ float lrelu(float x) { return x > 0.0f ? x : 0.01f * x; }

__device__ __forceinline__ unsigned smem_u32(const void* p) {
    return (unsigned)__cvta_generic_to_shared(p);
}

// ---------------- prep: deg=1 (self loop), cnt=0 ----------------
__global__ void k_prep() {
    int i = blockIdx.x * 256 + threadIdx.x;
    if (i < NN) { g_deg[i] = 1.0f; g_cnt[i] = 0; }
}

// ---------------- hist: deg only (count moved into fill) ----------------
__global__ void k_hist(const int* __restrict__ dst, const float* __restrict__ ew) {
    int e = blockIdx.x * 256 + threadIdx.x;
    if (e < EE) atomicAdd(&g_deg[dst[e]], ew[e]);
}

__global__ void k_dinv() {
    int i = blockIdx.x * 256 + threadIdx.x;
    if (i < NN) g_dinv[i] = rsqrtf(g_deg[i]);
}

// ---------------- CSR fill into fixed-capacity buckets; packed int2 -----------
__global__ void k_fill(const int* __restrict__ src, const int* __restrict__ dst,
                       const float* __restrict__ ew) {
    int e = blockIdx.x * 256 + threadIdx.x;
    if (e < EE) {
        int s = src[e], d = dst[e];
        int pos = atomicAdd(&g_cnt[d], 1);
        float coef = g_dinv[s] * ew[e] * g_dinv[d];
        g_ecsr[(d << CAPSH) + pos] = make_int2(s, __float_as_int(coef));
    }
}

// ---------------- tensor-core GEMM: [M,128](TIN,lrelu?) x [128,128] -> fp16 ----
// 256 threads / 8 warps. Block tile 128x128; warp tile 32x64.
// A and W staged fp16 in smem, row pad 136 halves (272B) -> ldmatrix conflict-free.
#define PAD 136
template <bool LRELU, typename TIN>
__global__ __launch_bounds__(256)
void k_gemm_mma(const TIN* __restrict__ A, const float* __restrict__ Wm,
                __half* __restrict__ Hout, int M) {
    extern __shared__ __half smh[];
    __half* As = smh;              // [128][PAD]
    __half* Ws = smh + 128 * PAD;  // [128][PAD]  (row-major [k][n])

    const int tid = threadIdx.x;
    const int row0 = blockIdx.x * 128;

    // stage A -> fp16, fused lrelu, zero-pad OOB rows
#pragma unroll
    for (int it = tid; it < 128 * 32; it += 256) {
        int r = it >> 5, c4 = it & 31;
        int row = row0 + r;
        float x0 = 0.f, x1 = 0.f, x2 = 0.f, x3 = 0.f;
        if (row < M) {
            if (sizeof(TIN) == 4) {
                float4 v = *(const float4*)((const float*)A + (size_t)row * FF + c4 * 4);
                x0 = v.x; x1 = v.y; x2 = v.z; x3 = v.w;
            } else {
                uint2 rw = *(const uint2*)((const __half*)A + (size_t)row * FF + c4 * 4);
                float2 f0 = __half22float2(*reinterpret_cast<__half2*>(&rw.x));
                float2 f1 = __half22float2(*reinterpret_cast<__half2*>(&rw.y));
                x0 = f0.x; x1 = f0.y; x2 = f1.x; x3 = f1.y;
            }
            if (LRELU) { x0 = lrelu(x0); x1 = lrelu(x1); x2 = lrelu(x2); x3 = lrelu(x3); }
        }
        __half2 h01 = __floats2half2_rn(x0, x1);
        __half2 h23 = __floats2half2_rn(x2, x3);
        uint2 pk = make_uint2(*reinterpret_cast<unsigned*>(&h01),
                              *reinterpret_cast<unsigned*>(&h23));
        *(uint2*)(As + r * PAD + c4 * 4) = pk;
    }
    // stage W (fp32 -> fp16, row-major [k][n])
#pragma unroll
    for (int it = tid; it < 128 * 32; it += 256) {
        int k = it >> 5, n4 = it & 31;
        float4 v = *(const float4*)(Wm + (size_t)k * FF + n4 * 4);
        __half2 h01 = __floats2half2_rn(v.x, v.y);
        __half2 h23 = __floats2half2_rn(v.z, v.w);
        uint2 pk = make_uint2(*reinterpret_cast<unsigned*>(&h01),
                              *reinterpret_cast<unsigned*>(&h23));
        *(uint2*)(Ws + k * PAD + n4 * 4) = pk;
    }
    __syncthreads();

    const int lane = tid & 31;
    const int warp = tid >> 5;
    const int wm = warp & 3;    // 4 warps down M: rows wm*32
    const int wn = warp >> 2;   // 2 warps across N: cols wn*64

    float c[2][8][4];
#pragma unroll
    for (int mi = 0; mi < 2; mi++)
#pragma unroll
        for (int ni = 0; ni < 8; ni++)
#pragma unroll
            for (int j = 0; j < 4; j++) c[mi][ni][j] = 0.f;

    const int a_r = lane & 15;
    const int a_c = (lane >> 4) * 8;
    const int b_k = lane & 15;

#pragma unroll
    for (int ks = 0; ks < 8; ks++) {
        const int k0 = ks * 16;
        unsigned a[2][4];
#pragma unroll
        for (int mi = 0; mi < 2; mi++) {
            const __half* ap = As + (wm * 32 + mi * 16 + a_r) * PAD + k0 + a_c;
            asm volatile("ldmatrix.sync.aligned.m8n8.x4.shared.b16 {%0,%1,%2,%3}, [%4];"
                         : "=r"(a[mi][0]), "=r"(a[mi][1]), "=r"(a[mi][2]), "=r"(a[mi][3])
                         : "r"(smem_u32(ap)));
        }
        unsigned b[8][2];
#pragma unroll
        for (int ni = 0; ni < 8; ni++) {
            const __half* bp = Ws + (k0 + b_k) * PAD + wn * 64 + ni * 8;
            asm volatile("ldmatrix.sync.aligned.m8n8.x2.trans.shared.b16 {%0,%1}, [%2];"
                         : "=r"(b[ni][0]), "=r"(b[ni][1])
                         : "r"(smem_u32(bp)));
        }
#pragma unroll
        for (int mi = 0; mi < 2; mi++)
#pragma unroll
            for (int ni = 0; ni < 8; ni++) {
                asm volatile(
                    "mma.sync.aligned.m16n8k16.row.col.f32.f16.f16.f32 "
                    "{%0,%1,%2,%3}, {%4,%5,%6,%7}, {%8,%9}, {%0,%1,%2,%3};"
                    : "+f"(c[mi][ni][0]), "+f"(c[mi][ni][1]),
                      "+f"(c[mi][ni][2]), "+f"(c[mi][ni][3])
                    : "r"(a[mi][0]), "r"(a[mi][1]), "r"(a[mi][2]), "r"(a[mi][3]),
                      "r"(b[ni][0]), "r"(b[ni][1]));
            }
    }

    // epilogue: fp32 -> fp16, packed u32 stores
#pragma unroll
    for (int mi = 0; mi < 2; mi++) {
        int rbase = row0 + wm * 32 + mi * 16 + (lane >> 2);
#pragma unroll
        for (int ni = 0; ni < 8; ni++) {
            int col = wn * 64 + ni * 8 + (lane & 3) * 2;
            __half2 lo = __floats2half2_rn(c[mi][ni][0], c[mi][ni][1]);
            __half2 hi = __floats2half2_rn(c[mi][ni][2], c[mi][ni][3]);
            if (rbase < M)
                *(unsigned*)(Hout + (size_t)rbase * FF + col) =
                    *reinterpret_cast<unsigned*>(&lo);
            if (rbase + 8 < M)
                *(unsigned*)(Hout + (size_t)(rbase + 8) * FF + col) =
                    *reinterpret_cast<unsigned*>(&hi);
        }
    }
}

// ---------------- GEMM: [M,128](fp16,lrelu) x [128,20] -> fp16, f32x2 FMA -----
__global__ __launch_bounds__(128)
void k_gemm20(const __half* __restrict__ A, const float* __restrict__ Wm,
              __half* __restrict__ Hout, int M) {
    extern __shared__ float sm[];
    float* As = sm;             // 128 * 133
    float* Ws = sm + 128 * 133; // 128 * 20

    const int tid = threadIdx.x;

    for (int i = tid; i < FF * CC / 4; i += 128)
        ((float4*)Ws)[i] = ((const float4*)Wm)[i];

    const int row0 = blockIdx.x * 128;
    for (int i = tid; i < 128 * 32; i += 128) {
        int r = i >> 5, k4 = i & 31;
        float x0 = 0.f, x1 = 0.f, x2 = 0.f, x3 = 0.f;
        int row = row0 + r;
        if (row < M) {
            uint2 rw = *(const uint2*)(A + (size_t)row * FF + k4 * 4);
            float2 f0 = __half22float2(*reinterpret_cast<__half2*>(&rw.x));
            float2 f1 = __half22float2(*reinterpret_cast<__half2*>(&rw.y));
            x0 = lrelu(f0.x); x1 = lrelu(f0.y); x2 = lrelu(f1.x); x3 = lrelu(f1.y);
        }
        float* p = As + r * 133 + k4 * 4;
        p[0] = x0; p[1] = x1; p[2] = x2; p[3] = x3;
    }
    __syncthreads();

    unsigned long long acc2[10];
#pragma unroll
    for (int j = 0; j < 10; j++) acc2[j] = 0ULL;

    const float* Ap = As + tid * 133;
#pragma unroll 4
    for (int k = 0; k < FF; k++) {
        float xv = Ap[k];
        unsigned xb = __float_as_uint(xv);
        unsigned long long av;
        asm("mov.b64 %0, {%1, %1};" : "=l"(av) : "r"(xb));
        const unsigned long long* wq =
            (const unsigned long long*)(Ws + k * CC);
#pragma unroll
        for (int j = 0; j < 10; j++) {
            asm("fma.rn.f32x2 %0, %1, %2, %0;" : "+l"(acc2[j]) : "l"(av), "l"(wq[j]));
        }
    }

    int row = row0 + tid;
    if (row < M) {
        // pack 20 fp32 -> 10 half2 -> 5 uint2 stores (row stride 40B, 8B aligned)
        unsigned pk[10];
#pragma unroll
        for (int j = 0; j < 10; j++) {
            unsigned lo, hi;
            asm("mov.b64 {%0, %1}, %2;" : "=r"(lo), "=r"(hi) : "l"(acc2[j]));
            __half2 h2 = __floats2half2_rn(__uint_as_float(lo), __uint_as_float(hi));
            pk[j] = *reinterpret_cast<unsigned*>(&h2);
        }
#pragma unroll
        for (int q = 0; q < 5; q++) {
            *(uint2*)(Hout + (size_t)row * CC + q * 4) = make_uint2(pk[2 * q], pk[2 * q + 1]);
        }
    }
}

// ---------------- CSR aggregation, 128-wide, fp16 gathers, warp per node ------
// DO NOT restructure this loop: one warp per node, 2-edge unroll is a verified
// codegen/scheduling optimum (rounds 5, 9, 14 regressions all came from
// restructuring it: array-batching, 4-wide, and 2-warp-split respectively).
template <bool GATHER>
__global__ __launch_bounds__(256)
void k_agg128(const __half* __restrict__ hh, const int* __restrict__ nid,
              const float* __restrict__ b, __half* __restrict__ out) {
    int warp = (blockIdx.x * 256 + threadIdx.x) >> 5;
    int lane = threadIdx.x & 31;
    if (warp >= NN) return;
    int cnt = g_cnt[warp];
    int beg = warp << CAPSH;

    float4 acc = make_float4(0.f, 0.f, 0.f, 0.f);
    int i = 0;
    int end2 = cnt & ~1;
    for (; i < end2; i += 2) {
        int2 e0 = g_ecsr[beg + i];
        int2 e1 = g_ecsr[beg + i + 1];
        int s0 = e0.x;
        int s1 = e1.x;
        float c0 = __int_as_float(e0.y);
        float c1 = __int_as_float(e1.y);
        if (GATHER) { s0 = nid[s0]; s1 = nid[s1]; }
        uint2 r0 = *(const uint2*)(hh + (size_t)s0 * FF + lane * 4);
        uint2 r1 = *(const uint2*)(hh + (size_t)s1 * FF + lane * 4);
        float2 f00 = __half22float2(*reinterpret_cast<__half2*>(&r0.x));
        float2 f01 = __half22float2(*reinterpret_cast<__half2*>(&r0.y));
        float2 f10 = __half22float2(*reinterpret_cast<__half2*>(&r1.x));
        float2 f11 = __half22float2(*reinterpret_cast<__half2*>(&r1.y));
        acc.x = fmaf(c0, f00.x, acc.x); acc.y = fmaf(c0, f00.y, acc.y);
        acc.z = fmaf(c0, f01.x, acc.z); acc.w = fmaf(c0, f01.y, acc.w);
        acc.x = fmaf(c1, f10.x, acc.x); acc.y = fmaf(c1, f10.y, acc.y);
        acc.z = fmaf(c1, f11.x, acc.z); acc.w = fmaf(c1, f11.y, acc.w);
    }
    if (i < cnt) {
        int2 e0 = g_ecsr[beg + i];
        int s0 = e0.x;
        float c0 = __int_as_float(e0.y);
        if (GATHER) s0 = nid[s0];
        uint2 r0 = *(const uint2*)(hh + (size_t)s0 * FF + lane * 4);
        float2 f00 = __half22float2(*reinterpret_cast<__half2*>(&r0.x));
        float2 f01 = __half22float2(*reinterpret_cast<__half2*>(&r0.y));
        acc.x = fmaf(c0, f00.x, acc.x); acc.y = fmaf(c0, f00.y, acc.y);
        acc.z = fmaf(c0, f01.x, acc.z); acc.w = fmaf(c0, f01.y, acc.w);
    }

    float di = g_dinv[warp];
    float d2 = di * di;
    int sn = GATHER ? nid[warp] : warp;
    uint2 rs = *(const uint2*)(hh + (size_t)sn * FF + lane * 4);
    float2 fs0 = __half22float2(*reinterpret_cast<__half2*>(&rs.x));
    float2 fs1 = __half22float2(*reinterpret_cast<__half2*>(&rs.y));
    float4 bv = *(const float4*)(b + lane * 4);
    acc.x = fmaf(fs0.x, d2, acc.x) + bv.x;
    acc.y = fmaf(fs0.y, d2, acc.y) + bv.y;
    acc.z = fmaf(fs1.x, d2, acc.z) + bv.z;
    acc.w = fmaf(fs1.y, d2, acc.w) + bv.w;
    __half2 o01 = __floats2half2_rn(acc.x, acc.y);
    __half2 o23 = __floats2half2_rn(acc.z, acc.w);
    uint2 pk = make_uint2(*reinterpret_cast<unsigned*>(&o01),
                          *reinterpret_cast<unsigned*>(&o23));
    *(uint2*)(out + (size_t)warp * FF + lane * 4) = pk;
}

// ---------------- CSR aggregation 20-wide (fp16 gathers) + log_softmax --------
__global__ __launch_bounds__(256)
void k_agg20_lsm(const float* __restrict__ b, float* __restrict__ out) {
    int warp = (blockIdx.x * 256 + threadIdx.x) >> 5;
    int lane = threadIdx.x & 31;
    if (warp >= NN) return;
    int cnt = g_cnt[warp];
    int beg = warp << CAPSH;

    float acc = 0.f;
    for (int i = 0; i < cnt; i++) {
        int2 e0 = g_ecsr[beg + i];
        if (lane < CC)
            acc = fmaf(__int_as_float(e0.y),
                       __half2float(g_h2[(size_t)e0.x * CC + lane]), acc);
    }
    float di = g_dinv[warp];
    float d2 = di * di;
    if (lane < CC)
        acc = fmaf(__half2float(g_h2[(size_t)warp * CC + lane]), d2, acc) + b[lane];

    float m = (lane < CC) ? acc : -1e30f;
#pragma unroll
    for (int off = 16; off > 0; off >>= 1)
        m = fmaxf(m, __shfl_xor_sync(0xffffffffu, m, off));
    float e = (lane < CC) ? expf(acc - m) : 0.f;
    float ssum = e;
#pragma unroll
    for (int off = 16; off > 0; off >>= 1)
        ssum += __shfl_xor_sync(0xffffffffu, ssum, off);
    float l = logf(ssum) + m;
    if (lane < CC)
        out[(size_t)warp * CC + lane] = acc - l;
}

// ---------------- launch ----------------
extern "C" void kernel_launch(void* const* d_in, const int* in_sizes, int n_in,
                              void* d_out, int out_size) {
    const int*   nid = (const int*)d_in[0];
    const int*   eidx = (const int*)d_in[1];
    const int*   src = eidx;
    const int*   dst = eidx + EE;
    const float* ew  = (const float*)d_in[2];
    const float* emb = (const float*)d_in[3];
    const float* W0  = (const float*)d_in[4];
    const float* b0  = (const float*)d_in[5];
    const float* W1  = (const float*)d_in[6];
    const float* b1  = (const float*)d_in[7];
    const float* W2  = (const float*)d_in[8];
    const float* b2  = (const float*)d_in[9];
    float* out = (float*)d_out;

    __half *p_embh, *p_hh, *p_act, *p_h2;
    cudaGetSymbolAddress((void**)&p_embh, g_embh);
    cudaGetSymbolAddress((void**)&p_hh,   g_hh);
    cudaGetSymbolAddress((void**)&p_act,  g_act);
    cudaGetSymbolAddress((void**)&p_h2,   g_h2);

    const int SMEM_MMA = 2 * 128 * PAD * (int)sizeof(__half);  // 69632 B
    const int SMEM_G20 = (128 * 133 + FF * CC) * 4;            // 78336 B
    cudaFuncSetAttribute((const void*)(k_gemm_mma<false, float>),
                         cudaFuncAttributeMaxDynamicSharedMemorySize, SMEM_MMA);
    cudaFuncSetAttribute((const void*)(k_gemm_mma<true, __half>),
                         cudaFuncAttributeMaxDynamicSharedMemorySize, SMEM_MMA);
    cudaFuncSetAttribute((const void*)k_gemm20,
                         cudaFuncAttributeMaxDynamicSharedMemorySize, SMEM_G20);

    // CSR build (no scan): prep -> hist(deg) -> dinv -> vocab GEMM -> fill
    k_prep<<<(NN + 255) / 256, 256>>>();
    k_hist<<<(EE + 255) / 256, 256>>>(dst, ew);
    k_dinv<<<(NN + 255) / 256, 256>>>();
    k_gemm_mma<false, float><<<(VV + 127) / 128, 256, SMEM_MMA>>>(emb, W0, p_embh, VV);
    k_fill<<<(EE + 255) / 256, 256>>>(src, dst, ew);

    // layer 0: aggregate straight from vocab-level embh via nid indirection
    k_agg128<true><<<(NN * 32 + 255) / 256, 256>>>(p_embh, nid, b0, p_act);

    // layer 1
    k_gemm_mma<true, __half><<<(NN + 127) / 128, 256, SMEM_MMA>>>(p_act, W1, p_hh, NN);
    k_agg128<false><<<(NN * 32 + 255) / 256, 256>>>(p_hh, nid, b1, p_act);

    // layer 2 + fused log_softmax
    k_gemm20<<<(NN + 127) / 128, 128, SMEM_G20>>>(p_act, W2, p_h2, NN);
    k_agg20_lsm<<<(NN * 32 + 255) / 256, 256>>>(b2, out);
}